// round 2
// baseline (speedup 1.0000x reference)
#include <cuda_runtime.h>
#include <math.h>

#define BS   4096
#define LEN  32
#define DIM  768
#define HID  384
#define ROWS (BS * LEN)          // 131072
#define LN_EPS 1e-5

// ---------------- scratch (device globals; no runtime allocation) ----------
__device__ float g_qa2[BS * DIM];          // 12.6 MB
__device__ float g_v2[ROWS * DIM];         // 402 MB
__device__ float g_mean_v[ROWS];
__device__ float g_rstd_v[ROWS];
__device__ float g_mean_qa[BS];
__device__ float g_rstd_qa[BS];
__device__ float g_m2[ROWS];               // mean(v2) per row
__device__ float g_alpha[ROWS];            // gate * rsqrt(gate^2 var + eps)
__device__ float g_logits[ROWS];

__device__ __forceinline__ float gelu_exact(float x) {
    return 0.5f * x * (1.0f + erff(x * 0.70710678118654752440f));
}

// ---------------- per-row mean / rstd (double accumulation) -----------------
__global__ void row_stats_kernel(const float* __restrict__ X,
                                 float* __restrict__ mean,
                                 float* __restrict__ rstd) {
    int row = blockIdx.x;
    const float* x = X + (size_t)row * DIM;
    double s = 0.0, ss = 0.0;
    for (int k = threadIdx.x; k < DIM; k += blockDim.x) {
        double v = (double)x[k];
        s += v; ss += v * v;
    }
    for (int o = 16; o; o >>= 1) {
        s  += __shfl_xor_sync(0xffffffffu, s,  o);
        ss += __shfl_xor_sync(0xffffffffu, ss, o);
    }
    __shared__ double sh1[8], sh2[8];
    int w = threadIdx.x >> 5, ln = threadIdx.x & 31;
    if (ln == 0) { sh1[w] = s; sh2[w] = ss; }
    __syncthreads();
    if (threadIdx.x == 0) {
        double S = 0.0, SS = 0.0;
        int nw = blockDim.x >> 5;
        for (int i = 0; i < nw; i++) { S += sh1[i]; SS += sh2[i]; }
        double m = S / DIM;
        double var = SS / DIM - m * m;
        if (var < 0.0) var = 0.0;
        mean[row] = (float)m;
        rstd[row] = (float)rsqrt(var + LN_EPS);
    }
}

// ---------------- SGEMM with fused LN on A, bias + gelu epilogue ------------
// C[M,N] = gelu( ((A[m,k]-mean[m])*rstd[m]*g[k]+b[k]) @ B[K,N] + bias[n] )
__global__ __launch_bounds__(256)
void gemm_kernel(const float* __restrict__ A, const float* __restrict__ B,
                 const float* __restrict__ rmean, const float* __restrict__ rrstd,
                 const float* __restrict__ lng, const float* __restrict__ lnb,
                 const float* __restrict__ bias,
                 float* __restrict__ C,
                 int M, int N, int K) {
    __shared__ float As[8][128];
    __shared__ float Bs[8][128];

    int tid = threadIdx.x;
    int tx = tid & 15, ty = tid >> 4;
    int bm = blockIdx.y * 128, bn = blockIdx.x * 128;

    int arow = tid >> 1;
    int acol = (tid & 1) * 4;
    int grow = bm + arow;
    float amean = rmean[grow];
    float arstd = rrstd[grow];
    const float* Aptr = A + (size_t)grow * K + acol;

    int brow = tid >> 5;
    int bcol = (tid & 31) * 4;
    const float* Bptr = B + (size_t)brow * N + bn + bcol;

    float acc[8][8];
#pragma unroll
    for (int i = 0; i < 8; i++)
#pragma unroll
        for (int j = 0; j < 8; j++) acc[i][j] = 0.f;

    for (int k0 = 0; k0 < K; k0 += 8) {
        float4 av = *(const float4*)(Aptr + k0);
        float4 lg = *(const float4*)(lng + k0 + acol);
        float4 lb = *(const float4*)(lnb + k0 + acol);
        As[acol + 0][arow] = (av.x - amean) * arstd * lg.x + lb.x;
        As[acol + 1][arow] = (av.y - amean) * arstd * lg.y + lb.y;
        As[acol + 2][arow] = (av.z - amean) * arstd * lg.z + lb.z;
        As[acol + 3][arow] = (av.w - amean) * arstd * lg.w + lb.w;
        *(float4*)&Bs[brow][bcol] = *(const float4*)(Bptr + (size_t)k0 * N);
        __syncthreads();

#pragma unroll
        for (int kk = 0; kk < 8; kk++) {
            float ra[8], rb[8];
            *(float4*)(ra)     = *(const float4*)&As[kk][ty * 8];
            *(float4*)(ra + 4) = *(const float4*)&As[kk][ty * 8 + 4];
            *(float4*)(rb)     = *(const float4*)&Bs[kk][tx * 8];
            *(float4*)(rb + 4) = *(const float4*)&Bs[kk][tx * 8 + 4];
#pragma unroll
            for (int i = 0; i < 8; i++)
#pragma unroll
                for (int j = 0; j < 8; j++) acc[i][j] += ra[i] * rb[j];
        }
        __syncthreads();
    }

    float bb[8];
#pragma unroll
    for (int j = 0; j < 8; j++) bb[j] = bias[bn + tx * 8 + j];

#pragma unroll
    for (int i = 0; i < 8; i++) {
        int row = bm + ty * 8 + i;
        float o[8];
#pragma unroll
        for (int j = 0; j < 8; j++) o[j] = gelu_exact(acc[i][j] + bb[j]);
        float* cp = C + (size_t)row * N + bn + tx * 8;
        *(float4*)(cp)     = *(float4*)(o);
        *(float4*)(cp + 4) = *(float4*)(o + 4);
    }
}

// ---------------- GEMM3: logits = b2 + gelu(LNfold(v2)@W1 + b1) . w2 --------
// One block per 128 rows; loops over all N=384 in-block; double dot
// accumulation; deterministic reduction (no atomics).
__global__ __launch_bounds__(256)
void gemm3_kernel(const float* __restrict__ A, const float* __restrict__ B,
                  const float* __restrict__ rmean, const float* __restrict__ rrstd,
                  const float* __restrict__ lng, const float* __restrict__ lnb,
                  const float* __restrict__ bias,
                  const float* __restrict__ w2, const float* __restrict__ b2,
                  float* __restrict__ logits) {
    __shared__ float As[8][128];
    __shared__ float Bs[8][128];
    __shared__ double sred[16][128];

    int tid = threadIdx.x;
    int tx = tid & 15, ty = tid >> 4;
    int bm = blockIdx.x * 128;

    int arow = tid >> 1;
    int acol = (tid & 1) * 4;
    int grow = bm + arow;
    float amean = rmean[grow];
    float arstd = rrstd[grow];
    const float* Aptr = A + (size_t)grow * DIM + acol;

    int brow = tid >> 5;
    int bcol = (tid & 31) * 4;

    double dsum[8];
#pragma unroll
    for (int i = 0; i < 8; i++) dsum[i] = 0.0;

    for (int n0 = 0; n0 < HID; n0 += 128) {
        const float* Bptr = B + (size_t)brow * HID + n0 + bcol;
        float acc[8][8];
#pragma unroll
        for (int i = 0; i < 8; i++)
#pragma unroll
            for (int j = 0; j < 8; j++) acc[i][j] = 0.f;

        for (int k0 = 0; k0 < DIM; k0 += 8) {
            float4 av = *(const float4*)(Aptr + k0);
            float4 lg = *(const float4*)(lng + k0 + acol);
            float4 lb = *(const float4*)(lnb + k0 + acol);
            As[acol + 0][arow] = (av.x - amean) * arstd * lg.x + lb.x;
            As[acol + 1][arow] = (av.y - amean) * arstd * lg.y + lb.y;
            As[acol + 2][arow] = (av.z - amean) * arstd * lg.z + lb.z;
            As[acol + 3][arow] = (av.w - amean) * arstd * lg.w + lb.w;
            *(float4*)&Bs[brow][bcol] = *(const float4*)(Bptr + (size_t)k0 * HID);
            __syncthreads();

#pragma unroll
            for (int kk = 0; kk < 8; kk++) {
                float ra[8], rb[8];
                *(float4*)(ra)     = *(const float4*)&As[kk][ty * 8];
                *(float4*)(ra + 4) = *(const float4*)&As[kk][ty * 8 + 4];
                *(float4*)(rb)     = *(const float4*)&Bs[kk][tx * 8];
                *(float4*)(rb + 4) = *(const float4*)&Bs[kk][tx * 8 + 4];
#pragma unroll
                for (int i = 0; i < 8; i++)
#pragma unroll
                    for (int j = 0; j < 8; j++) acc[i][j] += ra[i] * rb[j];
            }
            __syncthreads();
        }

        float bb[8], w2v[8];
#pragma unroll
        for (int j = 0; j < 8; j++) {
            bb[j]  = bias[n0 + tx * 8 + j];
            w2v[j] = w2[n0 + tx * 8 + j];
        }
#pragma unroll
        for (int i = 0; i < 8; i++) {
#pragma unroll
            for (int j = 0; j < 8; j++)
                dsum[i] += (double)gelu_exact(acc[i][j] + bb[j]) * (double)w2v[j];
        }
    }

#pragma unroll
    for (int i = 0; i < 8; i++) sred[tx][ty * 8 + i] = dsum[i];
    __syncthreads();
    if (tid < 128) {
        double s = 0.0;
#pragma unroll
        for (int t = 0; t < 16; t++) s += sred[t][tid];
        logits[bm + tid] = (float)(s + (double)b2[0]);
    }
}

// ---------------- gate = tanh(v2 . qa2); fold LN(v2*gate) into (m, alpha) ---
__global__ void gate_stats_kernel() {
    int row = blockIdx.x;
    int b = row >> 5;
    const float* v2 = g_v2 + (size_t)row * DIM;
    const float* q2 = g_qa2 + (size_t)b * DIM;
    double s = 0.0, ss = 0.0, dt = 0.0;
    for (int k = threadIdx.x; k < DIM; k += 256) {
        double a = (double)v2[k];
        s += a; ss += a * a; dt += a * (double)q2[k];
    }
    for (int o = 16; o; o >>= 1) {
        s  += __shfl_xor_sync(0xffffffffu, s,  o);
        ss += __shfl_xor_sync(0xffffffffu, ss, o);
        dt += __shfl_xor_sync(0xffffffffu, dt, o);
    }
    __shared__ double sh[3][8];
    int w = threadIdx.x >> 5, ln = threadIdx.x & 31;
    if (ln == 0) { sh[0][w] = s; sh[1][w] = ss; sh[2][w] = dt; }
    __syncthreads();
    if (threadIdx.x == 0) {
        double S = 0.0, SS = 0.0, DT = 0.0;
        for (int i = 0; i < 8; i++) { S += sh[0][i]; SS += sh[1][i]; DT += sh[2][i]; }
        double m = S / DIM;
        double var = SS / DIM - m * m;
        if (var < 0.0) var = 0.0;
        double gate = tanh(DT);
        g_m2[row] = (float)m;
        g_alpha[row] = (float)(gate * rsqrt(gate * gate * var + LN_EPS));
    }
}

// ---------------- finalize (double-precision decision chain) ----------------
// out layout (all fp32): gs[BS*LEN] | max_idx[BS*2] | start_t[BS] | end_t[BS]
//                        | mask[BS*LEN] | ori_key[BS*LEN]
#define OFF_GS     0
#define OFF_MAXIDX (BS * LEN)
#define OFF_START  (BS * LEN + BS * 2)
#define OFF_END    (BS * LEN + BS * 3)
#define OFF_MASK   (BS * LEN + BS * 4)
#define OFF_ORIKEY (BS * LEN * 2 + BS * 4)

__global__ void finalize_kernel(const float* __restrict__ sigma_ptr,
                                float* __restrict__ out) {
    const unsigned full = 0xffffffffu;
    int warp = threadIdx.x >> 5, lane = threadIdx.x & 31;
    int b = blockIdx.x * 8 + warp;
    if (b >= BS) return;

    float logit_f = g_logits[b * LEN + lane];
    double logit = (double)logit_f;

    // kp = softmax(logits)
    double m = logit;
    for (int o = 16; o; o >>= 1) m = fmax(m, __shfl_xor_sync(full, m, o));
    double e = exp(logit - m);
    double s = e;
    for (int o = 16; o; o >>= 1) s += __shfl_xor_sync(full, s, o);
    double kp = e / s;

    // gaussian kernel (sigma is a device scalar input)
    double sigma = (double)(*sigma_ptr);
    double kern[5];
    double ksum = 0.0;
#pragma unroll
    for (int j = 0; j < 5; j++) {
        double x = (double)(j - 2) / sigma;
        kern[j] = exp(-0.5 * x * x);
        ksum += kern[j];
    }
#pragma unroll
    for (int j = 0; j < 5; j++) kern[j] /= ksum;

    // zero-padded correlation over frames
    double sm = 0.0;
#pragma unroll
    for (int j = 0; j < 5; j++) {
        int src = lane + j - 2;
        double v = __shfl_sync(full, kp, src & 31);
        if (src >= 0 && src < LEN) sm += kern[j] * v;
    }

    // gs = softmax(sm)
    double mg = sm;
    for (int o = 16; o; o >>= 1) mg = fmax(mg, __shfl_xor_sync(full, mg, o));
    double eg = exp(sm - mg);
    double sg = eg;
    for (int o = 16; o; o >>= 1) sg += __shfl_xor_sync(full, sg, o);
    double gs = eg / sg;

    // first-occurrence argmax of gs
    double bv = gs; int bi = lane;
    for (int o = 16; o; o >>= 1) {
        double ov = __shfl_xor_sync(full, bv, o);
        int    oi = __shfl_xor_sync(full, bi, o);
        if (ov > bv || (ov == bv && oi < bi)) { bv = ov; bi = oi; }
    }
    int amax = bi;

    __shared__ double sgs[8][33];
    sgs[warp][lane] = gs;
    __syncwarp();

    int s0 = 0, e0 = 0;
    if (lane == 0) {
        double cs[LEN + 1];
        cs[0] = 0.0;
        for (int i = 0; i < LEN; i++) cs[i + 1] = cs[i] + sgs[warp][i];
        double best = -INFINITY;
        int bst = 0, bw = 1;
        const int ws[3] = {1, 3, 5};
        for (int wi = 0; wi < 3; wi++) {
            int w = ws[wi];
            for (int st = 0; st <= LEN - w; st++) {
                if (amax >= st && amax < st + w) {
                    double sc = cs[st + w] - cs[st];
                    if (sc > best) { best = sc; bst = st; bw = w; }
                }
            }
        }
        s0 = bst; e0 = bst + bw;
    }
    s0 = __shfl_sync(full, s0, 0);
    e0 = __shfl_sync(full, e0, 0);

    out[OFF_GS + b * LEN + lane] = (float)gs;
    if (lane == 0) {
        out[OFF_MAXIDX + b * 2 + 0] = (float)s0;
        out[OFF_MAXIDX + b * 2 + 1] = (float)e0;
        out[OFF_START + b] = (float)s0 / 31.0f;
        out[OFF_END + b]   = (float)e0 / 31.0f;
    }
    out[OFF_MASK + b * LEN + lane] = (lane >= s0 && lane <= e0) ? 1.f : 0.f;
    out[OFF_ORIKEY + b * LEN + lane] = logit_f;
}

// ---------------- launch ----------------------------------------------------
extern "C" void kernel_launch(void* const* d_in, const int* in_sizes, int n_in,
                              void* d_out, int out_size) {
    const float* v       = (const float*)d_in[0];
    const float* qa      = (const float*)d_in[1];
    const float* vp_g    = (const float*)d_in[2];
    const float* vp_b    = (const float*)d_in[3];
    const float* vp_W    = (const float*)d_in[4];
    const float* vp_bias = (const float*)d_in[5];
    const float* qp_g    = (const float*)d_in[6];
    const float* qp_b    = (const float*)d_in[7];
    const float* qp_W    = (const float*)d_in[8];
    const float* qp_bias = (const float*)d_in[9];
    const float* gr_g    = (const float*)d_in[10];
    const float* gr_b    = (const float*)d_in[11];
    const float* gr_W1   = (const float*)d_in[12];
    const float* gr_b1   = (const float*)d_in[13];
    const float* gr_W2   = (const float*)d_in[14];
    const float* gr_b2   = (const float*)d_in[15];
    const float* sigma   = (const float*)d_in[16];
    float* out = (float*)d_out;

    void *p_qa2, *p_v2, *p_mv, *p_rv, *p_mq, *p_rq, *p_m2, *p_al, *p_lg;
    cudaGetSymbolAddress(&p_qa2, g_qa2);
    cudaGetSymbolAddress(&p_v2,  g_v2);
    cudaGetSymbolAddress(&p_mv,  g_mean_v);
    cudaGetSymbolAddress(&p_rv,  g_rstd_v);
    cudaGetSymbolAddress(&p_mq,  g_mean_qa);
    cudaGetSymbolAddress(&p_rq,  g_rstd_qa);
    cudaGetSymbolAddress(&p_m2,  g_m2);
    cudaGetSymbolAddress(&p_al,  g_alpha);
    cudaGetSymbolAddress(&p_lg,  g_logits);

    // 1. row stats for qa and v
    row_stats_kernel<<<BS, 256>>>(qa, (float*)p_mq, (float*)p_rq);
    row_stats_kernel<<<ROWS, 256>>>(v, (float*)p_mv, (float*)p_rv);

    // 2. qa2 = gelu(LN(qa) @ qp_W + qp_bias)   [4096 x 768]
    gemm_kernel<<<dim3(DIM / 128, BS / 128), 256>>>(
        qa, qp_W, (const float*)p_mq, (const float*)p_rq, qp_g, qp_b, qp_bias,
        (float*)p_qa2, BS, DIM, DIM);

    // 3. v2 = gelu(LN(v) @ vp_W + vp_bias)     [131072 x 768]
    gemm_kernel<<<dim3(DIM / 128, ROWS / 128), 256>>>(
        v, vp_W, (const float*)p_mv, (const float*)p_rv, vp_g, vp_b, vp_bias,
        (float*)p_v2, ROWS, DIM, DIM);

    // 4. gate + folded LN stats for v2*gate
    gate_stats_kernel<<<ROWS, 256>>>();

    // 5. logits = b2 + gelu(LNfold(v2) @ gr_W1 + gr_b1) . gr_W2  (deterministic)
    gemm3_kernel<<<ROWS / 128, 256>>>(
        (const float*)p_v2, gr_W1, (const float*)p_m2, (const float*)p_al,
        gr_g, gr_b, gr_b1, gr_W2, gr_b2, (float*)p_lg);

    // 6. softmax -> gaussian conv -> softmax -> interval search -> outputs
    finalize_kernel<<<BS / 8, 256>>>(sigma, out);
}

// round 5
// speedup vs baseline: 2.1979x; 2.1979x over previous
#include <cuda_runtime.h>
#include <cuda_bf16.h>
#include <math.h>
#include <stdint.h>

#define BS   4096
#define LEN  32
#define DIM  768
#define HID  384
#define ROWS (BS * LEN)          // 131072
#define LN_EPS 1e-5f

// ---- mma tiling ----
#define BK 32
#define NCHUNK (DIM / BK)        // 24
#define ASTRIDE 40               // bf16 elems per smem row (pad: 80B, 16B-divisible)
#define TILE_B (128 * ASTRIDE * 2)   // 10240 bytes per split tile
#define SRED_OFF (12 * TILE_B)       // 122880
#define SMEM_DYN (SRED_OFF + 4 * 128 * 4)  // +2048 = 124928

// ---------------- scratch (device globals; no runtime allocation) ----------
__device__ float g_qa2[BS * DIM];
__device__ float g_v2[ROWS * DIM];
__device__ float g_mean_v[ROWS];
__device__ float g_rstd_v[ROWS];
__device__ float g_mean_qa[BS];
__device__ float g_rstd_qa[BS];
__device__ float g_m2[ROWS];
__device__ float g_alpha[ROWS];
__device__ float g_logits[ROWS];
// transposed+split weights, [split][n][k], 16B-aligned for uint4 loads
__device__ __align__(16) __nv_bfloat16 g_vpW_s[3 * DIM * DIM];
__device__ __align__(16) __nv_bfloat16 g_qpW_s[3 * DIM * DIM];
__device__ __align__(16) __nv_bfloat16 g_grW1_s[3 * HID * DIM];

__device__ __forceinline__ float gelu_exact(float x) {
    return 0.5f * x * (1.0f + erff(x * 0.70710678118654752440f));
}
// packs (lo, hi): low 16 bits = bf16(lo)
__device__ __forceinline__ uint32_t pack_bf16x2(float lo, float hi) {
    uint32_t r;
    asm("cvt.rn.satfinite.bf16x2.f32 %0, %1, %2;" : "=r"(r) : "f"(hi), "f"(lo));
    return r;
}
__device__ __forceinline__ void mma_bf16(float* d, const uint32_t* a, const uint32_t* b) {
    asm volatile(
        "mma.sync.aligned.m16n8k16.row.col.f32.bf16.bf16.f32 "
        "{%0,%1,%2,%3}, {%4,%5,%6,%7}, {%8,%9}, {%0,%1,%2,%3};"
        : "+f"(d[0]), "+f"(d[1]), "+f"(d[2]), "+f"(d[3])
        : "r"(a[0]), "r"(a[1]), "r"(a[2]), "r"(a[3]), "r"(b[0]), "r"(b[1]));
}

// ---------------- weight prepare: transpose + 3-way bf16 split --------------
// in: W[k][n] (K x N row-major).  out: Ws[s][n][k], s-stride = N*K
__global__ void prepare_w_kernel(const float* __restrict__ W,
                                 __nv_bfloat16* __restrict__ Ws,
                                 int K, int N) {
    int n = blockIdx.x;
    size_t ss = (size_t)N * K;
    for (int k = threadIdx.x; k < K; k += blockDim.x) {
        float x = W[(size_t)k * N + n];
        __nv_bfloat16 hb = __float2bfloat16_rn(x);
        float r = x - __bfloat162float(hb);
        __nv_bfloat16 mb = __float2bfloat16_rn(r);
        float r2 = r - __bfloat162float(mb);
        __nv_bfloat16 lb = __float2bfloat16_rn(r2);
        size_t o = (size_t)n * K + k;
        Ws[o] = hb; Ws[ss + o] = mb; Ws[2 * ss + o] = lb;
    }
}

// ---------------- per-row mean / rstd (warp per row, fp32) ------------------
__global__ void row_stats_kernel(const float* __restrict__ X,
                                 float* __restrict__ mean,
                                 float* __restrict__ rstd, int nrows) {
    int row = blockIdx.x * 8 + (threadIdx.x >> 5);
    if (row >= nrows) return;
    int lane = threadIdx.x & 31;
    const float* x = X + (size_t)row * DIM;
    float s = 0.f, ss = 0.f;
    for (int k = lane; k < DIM; k += 32) {
        float v = x[k];
        s += v; ss = fmaf(v, v, ss);
    }
    for (int o = 16; o; o >>= 1) {
        s  += __shfl_xor_sync(0xffffffffu, s,  o);
        ss += __shfl_xor_sync(0xffffffffu, ss, o);
    }
    if (lane == 0) {
        float m = s / DIM;
        float var = fmaxf(ss / DIM - m * m, 0.f);
        mean[row] = m;
        rstd[row] = rsqrtf(var + LN_EPS);
    }
}

// ---------------- gate = tanh(v2 . qa2); fold LN(v2*gate) -------------------
__global__ void gate_stats_kernel() {
    int row = blockIdx.x * 8 + (threadIdx.x >> 5);
    if (row >= ROWS) return;
    int lane = threadIdx.x & 31;
    int b = row >> 5;
    const float* v2 = g_v2 + (size_t)row * DIM;
    const float* q2 = g_qa2 + (size_t)b * DIM;
    float s = 0.f, ss = 0.f, dt = 0.f;
    for (int k = lane; k < DIM; k += 32) {
        float a = v2[k];
        s += a; ss = fmaf(a, a, ss); dt = fmaf(a, q2[k], dt);
    }
    for (int o = 16; o; o >>= 1) {
        s  += __shfl_xor_sync(0xffffffffu, s,  o);
        ss += __shfl_xor_sync(0xffffffffu, ss, o);
        dt += __shfl_xor_sync(0xffffffffu, dt, o);
    }
    if (lane == 0) {
        float m = s / DIM;
        float var = fmaxf(ss / DIM - m * m, 0.f);
        float gate = tanhf(dt);
        g_m2[row] = m;
        g_alpha[row] = gate * rsqrtf(gate * gate * var + LN_EPS);
    }
}

// ---------------- HMMA GEMM: C = gelu(LN(A)@B + bias), bf16x3x6 -------------
// EPI 0: write C tile (grid: [N/128, M/128])
// EPI 1: loop NT n-tiles in-block, fused dot with w2 -> logits (grid: [M/128])
template <int EPI>
__global__ __launch_bounds__(256, 1)
void mma_gemm_kernel(const float* __restrict__ A,
                     const __nv_bfloat16* __restrict__ Bsplit, size_t split_stride,
                     const float* __restrict__ rmean, const float* __restrict__ rrstd,
                     const float* __restrict__ lng, const float* __restrict__ lnb,
                     const float* __restrict__ bias,
                     float* __restrict__ C, int ldc,
                     const float* __restrict__ w2, const float* __restrict__ b2,
                     float* __restrict__ logits, int NT) {
    extern __shared__ char smem[];
    const unsigned full = 0xffffffffu;
    int tid = threadIdx.x;
    int wid = tid >> 5, lane = tid & 31;
    int warp_m = wid >> 2, warp_n = wid & 3;     // 2 x 4 warp grid
    int g = lane >> 2, tig = lane & 3;
    int bm = (EPI == 0 ? blockIdx.y : blockIdx.x) * 128;

    // prefetch mapping (A: 2 threads/row, 16 k each; B: 2 threads/row, 16 k each)
    int arow = tid >> 1, ahalf = tid & 1;
    float amean = rmean[bm + arow];
    float arstd = rrstd[bm + arow];
    const float* Aptr = A + (size_t)(bm + arow) * DIM + ahalf * 16;
    const float* gptr = lng + ahalf * 16;
    const float* bptr = lnb + ahalf * 16;

    float acc[4][4][4];
#pragma unroll
    for (int i = 0; i < 4; i++)
#pragma unroll
        for (int j = 0; j < 4; j++)
#pragma unroll
            for (int r = 0; r < 4; r++) acc[i][j][r] = 0.f;

    float xa[16];
    uint4 xb[3][2];

    const int NCH_TOT = NT * NCHUNK;
    float dotacc = 0.f;

    // ---- prefetch chunk cc into registers (LN fold applied to A) ----
    auto prefetch = [&](int cc) {
        int nt = cc / NCHUNK;
        int c  = cc % NCHUNK;
        int k0 = c * BK;
        int bn = (EPI == 0) ? blockIdx.x * 128 : nt * 128;
#pragma unroll
        for (int i = 0; i < 4; i++) {
            float4 a4 = *(const float4*)(Aptr + k0 + i * 4);
            float4 g4 = *(const float4*)(gptr + k0 + i * 4);
            float4 b4 = *(const float4*)(bptr + k0 + i * 4);
            xa[i * 4 + 0] = fmaf(a4.x - amean, arstd * g4.x, b4.x);
            xa[i * 4 + 1] = fmaf(a4.y - amean, arstd * g4.y, b4.y);
            xa[i * 4 + 2] = fmaf(a4.z - amean, arstd * g4.z, b4.z);
            xa[i * 4 + 3] = fmaf(a4.w - amean, arstd * g4.w, b4.w);
        }
        size_t boff = (size_t)(bn + arow) * DIM + k0 + ahalf * 16;
#pragma unroll
        for (int s = 0; s < 3; s++) {
            xb[s][0] = *(const uint4*)(Bsplit + s * split_stride + boff);
            xb[s][1] = *(const uint4*)(Bsplit + s * split_stride + boff + 8);
        }
    };

    // ---- split A regs to 3 bf16 tiles + copy B regs, into stage st ----
    auto store_stage = [&](int st) {
        char* base = smem + st * 6 * TILE_B;
#pragma unroll
        for (int i = 0; i < 4; i++) {
            float x0 = xa[i * 4], x1 = xa[i * 4 + 1], x2 = xa[i * 4 + 2], x3 = xa[i * 4 + 3];
            uint32_t p01 = pack_bf16x2(x0, x1), p23 = pack_bf16x2(x2, x3);
            float h0 = __uint_as_float(p01 << 16);
            float h1 = __uint_as_float(p01 & 0xFFFF0000u);
            float h2 = __uint_as_float(p23 << 16);
            float h3 = __uint_as_float(p23 & 0xFFFF0000u);
            float r0 = x0 - h0, r1 = x1 - h1, r2 = x2 - h2, r3 = x3 - h3;
            uint32_t q01 = pack_bf16x2(r0, r1), q23 = pack_bf16x2(r2, r3);
            float m0 = __uint_as_float(q01 << 16);
            float m1 = __uint_as_float(q01 & 0xFFFF0000u);
            float m2v = __uint_as_float(q23 << 16);
            float m3 = __uint_as_float(q23 & 0xFFFF0000u);
            uint32_t s01 = pack_bf16x2(r0 - m0, r1 - m1);
            uint32_t s23 = pack_bf16x2(r2 - m2v, r3 - m3);
            size_t off = (size_t)(arow * ASTRIDE + ahalf * 16 + i * 4) * 2;
            *(uint2*)(base + 0 * TILE_B + off) = make_uint2(p01, p23);
            *(uint2*)(base + 1 * TILE_B + off) = make_uint2(q01, q23);
            *(uint2*)(base + 2 * TILE_B + off) = make_uint2(s01, s23);
        }
        size_t boff = (size_t)(arow * ASTRIDE + ahalf * 16) * 2;
#pragma unroll
        for (int s = 0; s < 3; s++) {
            *(uint4*)(base + (3 + s) * TILE_B + boff) = xb[s][0];
            *(uint4*)(base + (3 + s) * TILE_B + boff + 16) = xb[s][1];
        }
    };

    // ---- compute one BK=32 chunk from stage st: 6 split-products ----
    auto compute = [&](int st) {
        char* base = smem + st * 6 * TILE_B;
#pragma unroll
        for (int ks = 0; ks < 2; ks++) {
            int kb = ks * 16 + tig * 2;
#pragma unroll
            for (int sa = 0; sa < 3; sa++) {
                const char* Ab = base + sa * TILE_B;
                uint32_t afr[4][4];
#pragma unroll
                for (int mt = 0; mt < 4; mt++) {
                    int r0 = warp_m * 64 + mt * 16 + g;
                    afr[mt][0] = *(const uint32_t*)(Ab + (size_t)(r0 * ASTRIDE + kb) * 2);
                    afr[mt][1] = *(const uint32_t*)(Ab + (size_t)((r0 + 8) * ASTRIDE + kb) * 2);
                    afr[mt][2] = *(const uint32_t*)(Ab + (size_t)(r0 * ASTRIDE + kb + 8) * 2);
                    afr[mt][3] = *(const uint32_t*)(Ab + (size_t)((r0 + 8) * ASTRIDE + kb + 8) * 2);
                }
#pragma unroll
                for (int sb = 0; sb < 3; sb++) {
                    if (sb >= 3 - sa) break;     // products: hh,hm,hl,mh,mm,lh
                    const char* Bb = base + (3 + sb) * TILE_B;
                    uint32_t bfr[4][2];
#pragma unroll
                    for (int nt2 = 0; nt2 < 4; nt2++) {
                        int n0 = warp_n * 32 + nt2 * 8 + g;
                        bfr[nt2][0] = *(const uint32_t*)(Bb + (size_t)(n0 * ASTRIDE + kb) * 2);
                        bfr[nt2][1] = *(const uint32_t*)(Bb + (size_t)(n0 * ASTRIDE + kb + 8) * 2);
                    }
#pragma unroll
                    for (int mt = 0; mt < 4; mt++)
#pragma unroll
                        for (int nt2 = 0; nt2 < 4; nt2++)
                            mma_bf16(acc[mt][nt2], afr[mt], bfr[nt2]);
                }
            }
        }
    };

    prefetch(0);
    store_stage(0);
    __syncthreads();

    for (int cc = 0; cc < NCH_TOT; cc++) {
        bool more = (cc + 1 < NCH_TOT);
        if (more) prefetch(cc + 1);
        compute(cc & 1);

        if (((cc + 1) % NCHUNK) == 0) {
            int nt = cc / NCHUNK;
            if (EPI == 0) {
                int bn = blockIdx.x * 128;
#pragma unroll
                for (int mt = 0; mt < 4; mt++) {
#pragma unroll
                    for (int nt2 = 0; nt2 < 4; nt2++) {
                        int row = bm + warp_m * 64 + mt * 16 + g;
                        int col = bn + warp_n * 32 + nt2 * 8 + tig * 2;
                        float2 v0, v1;
                        v0.x = gelu_exact(acc[mt][nt2][0] + bias[col]);
                        v0.y = gelu_exact(acc[mt][nt2][1] + bias[col + 1]);
                        v1.x = gelu_exact(acc[mt][nt2][2] + bias[col]);
                        v1.y = gelu_exact(acc[mt][nt2][3] + bias[col + 1]);
                        *(float2*)(C + (size_t)row * ldc + col) = v0;
                        *(float2*)(C + (size_t)(row + 8) * ldc + col) = v1;
                    }
                }
            } else {
                int bn = nt * 128;
                float part[4][2];
#pragma unroll
                for (int mt = 0; mt < 4; mt++) { part[mt][0] = 0.f; part[mt][1] = 0.f; }
#pragma unroll
                for (int mt = 0; mt < 4; mt++) {
#pragma unroll
                    for (int nt2 = 0; nt2 < 4; nt2++) {
                        int n0 = bn + warp_n * 32 + nt2 * 8 + tig * 2;
                        float b0v = bias[n0], b1v = bias[n0 + 1];
                        float w0 = w2[n0], w1 = w2[n0 + 1];
                        part[mt][0] += gelu_exact(acc[mt][nt2][0] + b0v) * w0
                                     + gelu_exact(acc[mt][nt2][1] + b1v) * w1;
                        part[mt][1] += gelu_exact(acc[mt][nt2][2] + b0v) * w0
                                     + gelu_exact(acc[mt][nt2][3] + b1v) * w1;
                        acc[mt][nt2][0] = 0.f; acc[mt][nt2][1] = 0.f;
                        acc[mt][nt2][2] = 0.f; acc[mt][nt2][3] = 0.f;
                    }
                }
#pragma unroll
                for (int off = 1; off <= 2; off <<= 1) {
#pragma unroll
                    for (int mt = 0; mt < 4; mt++) {
                        part[mt][0] += __shfl_xor_sync(full, part[mt][0], off);
                        part[mt][1] += __shfl_xor_sync(full, part[mt][1], off);
                    }
                }
                float* sr = (float*)(smem + SRED_OFF);
                if (tig == 0) {
#pragma unroll
                    for (int mt = 0; mt < 4; mt++) {
                        int r = warp_m * 64 + mt * 16 + g;
                        sr[warp_n * 128 + r] = part[mt][0];
                        sr[warp_n * 128 + r + 8] = part[mt][1];
                    }
                }
                __syncthreads();
                if (tid < 128)
                    dotacc += ((sr[tid] + sr[128 + tid]) + (sr[256 + tid] + sr[384 + tid]));
                __syncthreads();
            }
        }

        if (more) store_stage((cc + 1) & 1);
        __syncthreads();
    }

    if (EPI == 1 && tid < 128)
        logits[bm + tid] = dotacc + b2[0];
}

// ---------------- finalize (double-precision decision chain) ----------------
#define OFF_GS     0
#define OFF_MAXIDX (BS * LEN)
#define OFF_START  (BS * LEN + BS * 2)
#define OFF_END    (BS * LEN + BS * 3)
#define OFF_MASK   (BS * LEN + BS * 4)
#define OFF_ORIKEY (BS * LEN * 2 + BS * 4)

__global__ void finalize_kernel(const float* __restrict__ sigma_ptr,
                                float* __restrict__ out) {
    const unsigned full = 0xffffffffu;
    int warp = threadIdx.x >> 5, lane = threadIdx.x & 31;
    int b = blockIdx.x * 8 + warp;
    if (b >= BS) return;

    float logit_f = g_logits[b * LEN + lane];
    double logit = (double)logit_f;

    double m = logit;
    for (int o = 16; o; o >>= 1) m = fmax(m, __shfl_xor_sync(full, m, o));
    double e = exp(logit - m);
    double s = e;
    for (int o = 16; o; o >>= 1) s += __shfl_xor_sync(full, s, o);
    double kp = e / s;

    double sigma = (double)(*sigma_ptr);
    double kern[5];
    double ksum = 0.0;
#pragma unroll
    for (int j = 0; j < 5; j++) {
        double x = (double)(j - 2) / sigma;
        kern[j] = exp(-0.5 * x * x);
        ksum += kern[j];
    }
#pragma unroll
    for (int j = 0; j < 5; j++) kern[j] /= ksum;

    double sm = 0.0;
#pragma unroll
    for (int j = 0; j < 5; j++) {
        int src = lane + j - 2;
        double v = __shfl_sync(full, kp, src & 31);
        if (src >= 0 && src < LEN) sm += kern[j] * v;
    }

    double mg = sm;
    for (int o = 16; o; o >>= 1) mg = fmax(mg, __shfl_xor_sync(full, mg, o));
    double eg = exp(sm - mg);
    double sg = eg;
    for (int o = 16; o; o >>= 1) sg += __shfl_xor_sync(full, sg, o);
    double gs = eg / sg;

    double bv = gs; int bi = lane;
    for (int o = 16; o; o >>= 1) {
        double ov = __shfl_xor_sync(full, bv, o);
        int    oi = __shfl_xor_sync(full, bi, o);
        if (ov > bv || (ov == bv && oi < bi)) { bv = ov; bi = oi; }
    }
    int amax = bi;

    __shared__ double sgs[8][33];
    sgs[warp][lane] = gs;
    __syncwarp();

    int s0 = 0, e0 = 0;
    if (lane == 0) {
        double cs[LEN + 1];
        cs[0] = 0.0;
        for (int i = 0; i < LEN; i++) cs[i + 1] = cs[i] + sgs[warp][i];
        double best = -INFINITY;
        int bst = 0, bw = 1;
        const int ws[3] = {1, 3, 5};
        for (int wi = 0; wi < 3; wi++) {
            int w = ws[wi];
            for (int st = 0; st <= LEN - w; st++) {
                if (amax >= st && amax < st + w) {
                    double sc = cs[st + w] - cs[st];
                    if (sc > best) { best = sc; bst = st; bw = w; }
                }
            }
        }
        s0 = bst; e0 = bst + bw;
    }
    s0 = __shfl_sync(full, s0, 0);
    e0 = __shfl_sync(full, e0, 0);

    out[OFF_GS + b * LEN + lane] = (float)gs;
    if (lane == 0) {
        out[OFF_MAXIDX + b * 2 + 0] = (float)s0;
        out[OFF_MAXIDX + b * 2 + 1] = (float)e0;
        out[OFF_START + b] = (float)s0 / 31.0f;
        out[OFF_END + b]   = (float)e0 / 31.0f;
    }
    out[OFF_MASK + b * LEN + lane] = (lane >= s0 && lane <= e0) ? 1.f : 0.f;
    out[OFF_ORIKEY + b * LEN + lane] = logit_f;
}

// ---------------- launch ----------------------------------------------------
extern "C" void kernel_launch(void* const* d_in, const int* in_sizes, int n_in,
                              void* d_out, int out_size) {
    const float* v       = (const float*)d_in[0];
    const float* qa      = (const float*)d_in[1];
    const float* vp_g    = (const float*)d_in[2];
    const float* vp_b    = (const float*)d_in[3];
    const float* vp_W    = (const float*)d_in[4];
    const float* vp_bias = (const float*)d_in[5];
    const float* qp_g    = (const float*)d_in[6];
    const float* qp_b    = (const float*)d_in[7];
    const float* qp_W    = (const float*)d_in[8];
    const float* qp_bias = (const float*)d_in[9];
    const float* gr_g    = (const float*)d_in[10];
    const float* gr_b    = (const float*)d_in[11];
    const float* gr_W1   = (const float*)d_in[12];
    const float* gr_b1   = (const float*)d_in[13];
    const float* gr_W2   = (const float*)d_in[14];
    const float* gr_b2   = (const float*)d_in[15];
    const float* sigma   = (const float*)d_in[16];
    float* out = (float*)d_out;

    void *p_qa2, *p_v2, *p_mv, *p_rv, *p_mq, *p_rq, *p_m2, *p_al, *p_lg;
    void *p_vpw, *p_qpw, *p_w1;
    cudaGetSymbolAddress(&p_qa2, g_qa2);
    cudaGetSymbolAddress(&p_v2,  g_v2);
    cudaGetSymbolAddress(&p_mv,  g_mean_v);
    cudaGetSymbolAddress(&p_rv,  g_rstd_v);
    cudaGetSymbolAddress(&p_mq,  g_mean_qa);
    cudaGetSymbolAddress(&p_rq,  g_rstd_qa);
    cudaGetSymbolAddress(&p_m2,  g_m2);
    cudaGetSymbolAddress(&p_al,  g_alpha);
    cudaGetSymbolAddress(&p_lg,  g_logits);
    cudaGetSymbolAddress(&p_vpw, g_vpW_s);
    cudaGetSymbolAddress(&p_qpw, g_qpW_s);
    cudaGetSymbolAddress(&p_w1,  g_grW1_s);

    __nv_bfloat16* vpw = (__nv_bfloat16*)p_vpw;
    __nv_bfloat16* qpw = (__nv_bfloat16*)p_qpw;
    __nv_bfloat16* w1s = (__nv_bfloat16*)p_w1;

    cudaFuncSetAttribute(mma_gemm_kernel<0>,
                         cudaFuncAttributeMaxDynamicSharedMemorySize, SMEM_DYN);
    cudaFuncSetAttribute(mma_gemm_kernel<1>,
                         cudaFuncAttributeMaxDynamicSharedMemorySize, SMEM_DYN);

    // 1. weight transpose + 3-way split
    prepare_w_kernel<<<DIM, 256>>>(vp_W, vpw, DIM, DIM);
    prepare_w_kernel<<<DIM, 256>>>(qp_W, qpw, DIM, DIM);
    prepare_w_kernel<<<HID, 256>>>(gr_W1, w1s, DIM, HID);

    // 2. row stats
    row_stats_kernel<<<BS / 8, 256>>>(qa, (float*)p_mq, (float*)p_rq, BS);
    row_stats_kernel<<<ROWS / 8, 256>>>(v, (float*)p_mv, (float*)p_rv, ROWS);

    // 3. qa2 = gelu(LN(qa) @ qp_W + qp_bias)
    mma_gemm_kernel<0><<<dim3(DIM / 128, BS / 128), 256, SMEM_DYN>>>(
        qa, qpw, (size_t)DIM * DIM,
        (const float*)p_mq, (const float*)p_rq, qp_g, qp_b, qp_bias,
        (float*)p_qa2, DIM, nullptr, nullptr, nullptr, 1);

    // 4. v2 = gelu(LN(v) @ vp_W + vp_bias)
    mma_gemm_kernel<0><<<dim3(DIM / 128, ROWS / 128), 256, SMEM_DYN>>>(
        v, vpw, (size_t)DIM * DIM,
        (const float*)p_mv, (const float*)p_rv, vp_g, vp_b, vp_bias,
        (float*)p_v2, DIM, nullptr, nullptr, nullptr, 1);

    // 5. gate + folded LN stats
    gate_stats_kernel<<<ROWS / 8, 256>>>();

    // 6. logits = b2 + gelu(LNfold(v2) @ gr_W1 + gr_b1) . gr_W2  (deterministic)
    mma_gemm_kernel<1><<<dim3(ROWS / 128), 256, SMEM_DYN>>>(
        (const float*)p_v2, w1s, (size_t)HID * DIM,
        (const float*)p_m2, (const float*)p_al, gr_g, gr_b, gr_b1,
        nullptr, 0, gr_W2, gr_b2, (float*)p_lg, HID / 128);

    // 7. softmax -> conv -> softmax -> interval -> outputs
    finalize_kernel<<<BS / 8, 256>>>(sigma, out);
}